// round 9
// baseline (speedup 1.0000x reference)
#include <cuda_runtime.h>
#include <cuda_bf16.h>
#include <cstdint>

// ============================================================================
// SSIM loss via warp-level bf16 MMA (mma.sync m16n8k16) on the tensor pipe,
// with split-precision weights W = W_hi + W_lo (both bf16) so the banded
// Gaussian matrix carries ~fp32 effective precision.
//
// Per tile (64x64, one per block) per channel:
//   A1[(sig,r)][c] = bf16 signals u=x+y, v=x-y, u^2, v^2      (256 x 64)
//   GEMM1: D1 = A1 * W^T        (horizontal 11-tap conv)      band-pruned
//   C1 = bf16(D1) stored in place of A1 (warp-owned rows)
//   GEMM2: D2 = W * C1^T        (vertical 11-tap conv)        band-pruned
//   epilogue: 4 sigs at identical fragment positions -> in-thread ssim.
// Buffers live in DYNAMIC smem (static cap is 48KB).
// ============================================================================

static constexpr int THREADS = 256;
static constexpr int NBLK    = 2048;
static constexpr float C1c = 1.0e-4f;
static constexpr float C2c = 9.0e-4f;

// dynamic smem offsets (base is 1024-aligned)
static constexpr int OFF_A   = 0;        // 256 rows x 128B  = 32768
static constexpr int OFF_WH  = 32768;    //  64 rows x 128B  =  8192
static constexpr int OFF_WL  = 40960;    //  64 rows x 128B  =  8192
static constexpr int SMEM_BYTES = 49152;

__device__ const float Gk[11] = {
    0.00102840f, 0.00759878f, 0.03600077f, 0.10936042f, 0.21300560f,
    0.26601170f,
    0.21300560f, 0.10936042f, 0.03600077f, 0.00759878f, 0.00102840f
};

__device__ float        g_part[NBLK];
__device__ unsigned int g_count = 0;

// ---------------- helpers ----------------
__device__ __forceinline__ uint32_t smem_u32(const void* p) {
    uint32_t a;
    asm("{ .reg .u64 t; cvta.to.shared.u64 t, %1; cvt.u32.u64 %0, t; }"
        : "=r"(a) : "l"(p));
    return a;
}
// 128B-row buffer, XOR swizzle on bits 4..6 keyed by row%8.
__device__ __forceinline__ uint32_t swz(int row, int colb) {
    return (uint32_t)(row * 128 + (colb ^ ((row & 7) << 4)));
}
__device__ __forceinline__ uint32_t pk_bf(float hi, float lo) {
    uint32_t r;
    asm("cvt.rn.bf16x2.f32 %0, %1, %2;" : "=r"(r) : "f"(hi), "f"(lo));
    return r;
}
__device__ __forceinline__ void sts32(uint32_t addr, uint32_t v) {
    asm volatile("st.shared.b32 [%0], %1;" :: "r"(addr), "r"(v));
}
__device__ __forceinline__ void sts16(uint32_t addr, unsigned short v) {
    asm volatile("st.shared.b16 [%0], %1;" :: "r"(addr), "h"(v));
}
__device__ __forceinline__ void ldm_x4(uint32_t* r, uint32_t a) {
    asm volatile("ldmatrix.sync.aligned.m8n8.x4.shared.b16 {%0,%1,%2,%3}, [%4];"
                 : "=r"(r[0]), "=r"(r[1]), "=r"(r[2]), "=r"(r[3]) : "r"(a));
}
__device__ __forceinline__ void ldm_x2(uint32_t* r, uint32_t a) {
    asm volatile("ldmatrix.sync.aligned.m8n8.x2.shared.b16 {%0,%1}, [%2];"
                 : "=r"(r[0]), "=r"(r[1]) : "r"(a));
}
__device__ __forceinline__ void ldm_x2t(uint32_t* r, uint32_t a) {
    asm volatile("ldmatrix.sync.aligned.m8n8.x2.trans.shared.b16 {%0,%1}, [%2];"
                 : "=r"(r[0]), "=r"(r[1]) : "r"(a));
}
__device__ __forceinline__ void mma16816(float* c, const uint32_t* a,
                                         const uint32_t* b) {
    asm volatile(
        "mma.sync.aligned.m16n8k16.row.col.f32.bf16.bf16.f32 "
        "{%0,%1,%2,%3}, {%4,%5,%6,%7}, {%8,%9}, {%0,%1,%2,%3};"
        : "+f"(c[0]), "+f"(c[1]), "+f"(c[2]), "+f"(c[3])
        : "r"(a[0]), "r"(a[1]), "r"(a[2]), "r"(a[3]), "r"(b[0]), "r"(b[1]));
}

__global__ __launch_bounds__(THREADS, 2)
void ssim_main(const float* __restrict__ pred, const float* __restrict__ gt,
               float* __restrict__ out)
{
    extern __shared__ __align__(1024) uint8_t dyn[];
    __shared__ float red[THREADS / 32];
    __shared__ unsigned int ticket;

    const uint32_t SB  = smem_u32(dyn);
    const uint32_t AB  = SB + OFF_A;
    const uint32_t WB  = SB + OFF_WH;
    const uint32_t WLB = SB + OFF_WL;

    const int tid  = threadIdx.x;
    const int warp = tid >> 5;
    const int lane = tid & 31;
    const int g    = lane >> 2;       // 0..7
    const int tig  = lane & 3;        // 0..3

    const float* pb = pred + (size_t)blockIdx.x * 12288;
    const float* gb = gt   + (size_t)blockIdx.x * 12288;

    // ---- build W split: W[n][k] = G[k-n], rows n>=54 zero
    for (int i = tid; i < 4096; i += THREADS) {
        const int n = i >> 6, k = i & 63, d = k - n;
        float w = 0.0f;
        if (n < 54 && d >= 0 && d < 11) w = Gk[d];
        const __nv_bfloat16 whi = __float2bfloat16(w);
        const __nv_bfloat16 wlo = __float2bfloat16(w - __bfloat162float(whi));
        sts16(WB  + swz(n, k * 2), *(const unsigned short*)&whi);
        sts16(WLB + swz(n, k * 2), *(const unsigned short*)&wlo);
    }
    __syncthreads();

    // band lists: GEMM1 n-tiles touched per k-tile
    const int jl_start[4] = {0, 0, 2, 4};
    const int jl_cnt  [4] = {2, 4, 4, 4};

    float local = 0.0f;

    for (int ch = 0; ch < 3; ++ch) {
        __syncthreads();   // all warps done reading C1 from previous channel

        // ================= build A1: rows sig*64+r, cols c ================
        for (int idx = tid; idx < 2048; idx += THREADS) {
            const int pix = idx * 2;
            const int r = pix >> 6, c = pix & 63;
            const float x0 = pb[pix * 3 + ch],     y0 = gb[pix * 3 + ch];
            const float x1 = pb[pix * 3 + 3 + ch], y1 = gb[pix * 3 + 3 + ch];
            const float u0 = x0 + y0, v0 = x0 - y0;
            const float u1 = x1 + y1, v1 = x1 - y1;
            sts32(AB + swz(r,       c * 2), pk_bf(u1, u0));
            sts32(AB + swz(64 + r,  c * 2), pk_bf(v1, v0));
            sts32(AB + swz(128 + r, c * 2), pk_bf(u1 * u1, u0 * u0));
            sts32(AB + swz(192 + r, c * 2), pk_bf(v1 * v1, v0 * v0));
        }
        __syncthreads();

        // ================= GEMM1 (horizontal): warp owns rows warp*32.. ===
        {
            const int m0 = warp * 32;
            float acc[2][8][4];
            #pragma unroll
            for (int mi = 0; mi < 2; ++mi)
                #pragma unroll
                for (int j = 0; j < 8; ++j)
                    #pragma unroll
                    for (int e = 0; e < 4; ++e) acc[mi][j][e] = 0.0f;

            #pragma unroll
            for (int kt = 0; kt < 4; ++kt) {
                uint32_t af[2][4];
                #pragma unroll
                for (int mi = 0; mi < 2; ++mi) {
                    const int row  = m0 + mi * 16 + (lane & 15);
                    const int colb = kt * 32 + (lane >> 4) * 16;
                    ldm_x4(af[mi], AB + swz(row, colb));
                }
                #pragma unroll
                for (int jj = 0; jj < 4; ++jj) {
                    if (jj >= jl_cnt[kt]) break;
                    const int j = jl_start[kt] + jj;
                    const int nrow = 8 * j + (lane & 7);
                    const int colb = kt * 32 + ((lane >> 3) & 1) * 16;
                    uint32_t bh[2], bl[2];
                    ldm_x2(bh, WB  + swz(nrow, colb));
                    ldm_x2(bl, WLB + swz(nrow, colb));
                    mma16816(acc[0][j], af[0], bh);
                    mma16816(acc[1][j], af[1], bh);
                    mma16816(acc[0][j], af[0], bl);
                    mma16816(acc[1][j], af[1], bl);
                }
            }
            // store C1 = bf16(D1) in place (warp-owned rows; no race)
            #pragma unroll
            for (int mi = 0; mi < 2; ++mi) {
                const int r0 = m0 + mi * 16 + g;
                #pragma unroll
                for (int j = 0; j < 8; ++j) {
                    const int colb = j * 16 + tig * 4;
                    sts32(AB + swz(r0,     colb), pk_bf(acc[mi][j][1], acc[mi][j][0]));
                    sts32(AB + swz(r0 + 8, colb), pk_bf(acc[mi][j][3], acc[mi][j][2]));
                }
            }
        }
        __syncthreads();

        // ================= GEMM2 (vertical) + epilogue ====================
        {
            const int mh = warp & 1;       // m half: rows 32*mh..
            const int nq = warp >> 1;      // n quarter: cols 16*nq..
            float acc2[4][2][2][4];
            #pragma unroll
            for (int s = 0; s < 4; ++s)
                #pragma unroll
                for (int mi = 0; mi < 2; ++mi)
                    #pragma unroll
                    for (int nn = 0; nn < 2; ++nn)
                        #pragma unroll
                        for (int e = 0; e < 4; ++e) acc2[s][mi][nn][e] = 0.0f;

            #pragma unroll
            for (int kt = 0; kt < 4; ++kt) {
                uint32_t ah[2][4], al[2][4];
                bool use[2];
                #pragma unroll
                for (int mi = 0; mi < 2; ++mi) {
                    const int mt = 2 * mh + mi;
                    use[mi] = (kt == mt) || (kt == mt + 1);
                    if (use[mi]) {
                        const int row  = mt * 16 + (lane & 15);
                        const int colb = kt * 32 + (lane >> 4) * 16;
                        ldm_x4(ah[mi], WB  + swz(row, colb));
                        ldm_x4(al[mi], WLB + swz(row, colb));
                    }
                }
                if (!use[0] && !use[1]) continue;
                #pragma unroll
                for (int s = 0; s < 4; ++s) {
                    #pragma unroll
                    for (int nn = 0; nn < 2; ++nn) {
                        uint32_t bf[2];
                        const int krow = kt * 16 + (lane & 15);
                        const int srow = s * 64 + krow;
                        const int colb = (2 * nq + nn) * 16;
                        ldm_x2t(bf, AB + swz(srow, colb));
                        if (use[0]) { mma16816(acc2[s][0][nn], ah[0], bf);
                                      mma16816(acc2[s][0][nn], al[0], bf); }
                        if (use[1]) { mma16816(acc2[s][1][nn], ah[1], bf);
                                      mma16816(acc2[s][1][nn], al[1], bf); }
                    }
                }
            }

            // epilogue: 4 sigs at identical positions -> in-thread ssim
            #pragma unroll
            for (int mi = 0; mi < 2; ++mi) {
                #pragma unroll
                for (int nn = 0; nn < 2; ++nn) {
                    const int m0e = 32 * mh + 16 * mi;
                    const int n0e = (2 * nq + nn) * 8;
                    #pragma unroll
                    for (int e = 0; e < 4; ++e) {
                        const int r = m0e + g + ((e >= 2) ? 8 : 0);
                        const int c = n0e + 2 * tig + (e & 1);
                        if (r < 54 && c < 54) {
                            const float p  = acc2[0][mi][nn][e];
                            const float q  = acc2[1][mi][nn][e];
                            const float su = acc2[2][mi][nn][e];
                            const float sv = acc2[3][mi][nn][e];
                            const float P = p * p, Q = q * q;
                            const float A = 0.5f * (P - Q);
                            const float B = 0.5f * (P + Q);
                            const float num = (A + C1c) * (fmaf(0.5f, su - sv, C2c) - A);
                            const float den = (B + C1c) * (fmaf(0.5f, su + sv, C2c) - B);
                            local += __fdividef(num, den);
                        }
                    }
                }
            }
        }
    }

    // ================= deterministic reduction ============================
    __syncthreads();
    #pragma unroll
    for (int off = 16; off > 0; off >>= 1)
        local += __shfl_down_sync(0xffffffffu, local, off);
    if (lane == 0) red[warp] = local;
    __syncthreads();
    if (tid == 0) {
        float sum = 0.0f;
        #pragma unroll
        for (int w = 0; w < THREADS / 32; ++w) sum += red[w];
        g_part[blockIdx.x] = sum;
        __threadfence();
        ticket = atomicAdd(&g_count, 1u);
    }
    __syncthreads();

    if (ticket == NBLK - 1) {
        float sum = 0.0f;
        for (int i = tid; i < NBLK; i += THREADS) sum += g_part[i];
        #pragma unroll
        for (int off = 16; off > 0; off >>= 1)
            sum += __shfl_down_sync(0xffffffffu, sum, off);
        if (lane == 0) red[warp] = sum;
        __syncthreads();
        if (tid == 0) {
            float t = 0.0f;
            #pragma unroll
            for (int w = 0; w < THREADS / 32; ++w) t += red[w];
            out[0] = 1.0f - t * (1.0f / 17915904.0f);   // 2048*3*54*54
            g_count = 0;                                 // reset for replay
        }
    }
}

extern "C" void kernel_launch(void* const* d_in, const int* in_sizes, int n_in,
                              void* d_out, int out_size)
{
    const float* pred = (const float*)d_in[0];
    const float* gt   = (const float*)d_in[1];
    float* out        = (float*)d_out;

    cudaFuncSetAttribute(ssim_main, cudaFuncAttributeMaxDynamicSharedMemorySize,
                         SMEM_BYTES);
    ssim_main<<<NBLK, THREADS, SMEM_BYTES>>>(pred, gt, out);
}

// round 10
// speedup vs baseline: 1.1131x; 1.1131x over previous
#include <cuda_runtime.h>
#include <cuda_bf16.h>
#include <cstdint>

// ============================================================================
// SSIM loss via warp-level bf16 MMA (mma.sync m16n8k16), split weights
// W = W_hi + W_lo for fp32-grade weight precision. Register-lean variant:
// GEMM1 loops m-halves, GEMM2 loops n-halves; ldmatrix batched ahead of MMAs;
// launch_bounds(256,3) for 3 CTAs/SM.
// ============================================================================

static constexpr int THREADS = 256;
static constexpr int NBLK    = 2048;
static constexpr float C1c = 1.0e-4f;
static constexpr float C2c = 9.0e-4f;

// dynamic smem offsets (base 1024-aligned)
static constexpr int OFF_A  = 0;        // 256 rows x 128B = 32768 (A1 / C1)
static constexpr int OFF_WH = 32768;    //  64 rows x 128B =  8192
static constexpr int OFF_WL = 40960;    //  64 rows x 128B =  8192
static constexpr int SMEM_BYTES = 49152;

__device__ const float Gk[11] = {
    0.00102840f, 0.00759878f, 0.03600077f, 0.10936042f, 0.21300560f,
    0.26601170f,
    0.21300560f, 0.10936042f, 0.03600077f, 0.00759878f, 0.00102840f
};

__device__ float        g_part[NBLK];
__device__ unsigned int g_count = 0;

// ---------------- helpers ----------------
__device__ __forceinline__ uint32_t smem_u32(const void* p) {
    uint32_t a;
    asm("{ .reg .u64 t; cvta.to.shared.u64 t, %1; cvt.u32.u64 %0, t; }"
        : "=r"(a) : "l"(p));
    return a;
}
__device__ __forceinline__ uint32_t swz(int row, int colb) {
    return (uint32_t)(row * 128 + (colb ^ ((row & 7) << 4)));
}
__device__ __forceinline__ uint32_t pk_bf(float hi, float lo) {
    uint32_t r;
    asm("cvt.rn.bf16x2.f32 %0, %1, %2;" : "=r"(r) : "f"(hi), "f"(lo));
    return r;
}
__device__ __forceinline__ void sts32(uint32_t addr, uint32_t v) {
    asm volatile("st.shared.b32 [%0], %1;" :: "r"(addr), "r"(v));
}
__device__ __forceinline__ void sts16(uint32_t addr, unsigned short v) {
    asm volatile("st.shared.b16 [%0], %1;" :: "r"(addr), "h"(v));
}
__device__ __forceinline__ void ldm_x4(uint32_t* r, uint32_t a) {
    asm volatile("ldmatrix.sync.aligned.m8n8.x4.shared.b16 {%0,%1,%2,%3}, [%4];"
                 : "=r"(r[0]), "=r"(r[1]), "=r"(r[2]), "=r"(r[3]) : "r"(a));
}
__device__ __forceinline__ void ldm_x2(uint32_t* r, uint32_t a) {
    asm volatile("ldmatrix.sync.aligned.m8n8.x2.shared.b16 {%0,%1}, [%2];"
                 : "=r"(r[0]), "=r"(r[1]) : "r"(a));
}
__device__ __forceinline__ void ldm_x2t(uint32_t* r, uint32_t a) {
    asm volatile("ldmatrix.sync.aligned.m8n8.x2.trans.shared.b16 {%0,%1}, [%2];"
                 : "=r"(r[0]), "=r"(r[1]) : "r"(a));
}
__device__ __forceinline__ void mma16816(float* c, const uint32_t* a,
                                         const uint32_t* b) {
    asm volatile(
        "mma.sync.aligned.m16n8k16.row.col.f32.bf16.bf16.f32 "
        "{%0,%1,%2,%3}, {%4,%5,%6,%7}, {%8,%9}, {%0,%1,%2,%3};"
        : "+f"(c[0]), "+f"(c[1]), "+f"(c[2]), "+f"(c[3])
        : "r"(a[0]), "r"(a[1]), "r"(a[2]), "r"(a[3]), "r"(b[0]), "r"(b[1]));
}

__global__ __launch_bounds__(THREADS, 3)
void ssim_main(const float* __restrict__ pred, const float* __restrict__ gt,
               float* __restrict__ out)
{
    extern __shared__ __align__(1024) uint8_t dyn[];
    __shared__ float red[THREADS / 32];
    __shared__ unsigned int ticket;

    const uint32_t SB  = smem_u32(dyn);
    const uint32_t AB  = SB + OFF_A;
    const uint32_t WB  = SB + OFF_WH;
    const uint32_t WLB = SB + OFF_WL;

    const int tid  = threadIdx.x;
    const int warp = tid >> 5;
    const int lane = tid & 31;
    const int g    = lane >> 2;
    const int tig  = lane & 3;

    const float* pb = pred + (size_t)blockIdx.x * 12288;
    const float* gb = gt   + (size_t)blockIdx.x * 12288;

    // ---- build W split: W[n][k] = G[k-n], rows n>=54 zero
    for (int i = tid; i < 4096; i += THREADS) {
        const int n = i >> 6, k = i & 63, d = k - n;
        float w = 0.0f;
        if (n < 54 && d >= 0 && d < 11) w = Gk[d];
        const __nv_bfloat16 whi = __float2bfloat16(w);
        const __nv_bfloat16 wlo = __float2bfloat16(w - __bfloat162float(whi));
        sts16(WB  + swz(n, k * 2), *(const unsigned short*)&whi);
        sts16(WLB + swz(n, k * 2), *(const unsigned short*)&wlo);
    }
    __syncthreads();

    float local = 0.0f;

    for (int ch = 0; ch < 3; ++ch) {
        __syncthreads();   // prior GEMM2 done reading C1

        // ================= build A1: rows sig*64+r, cols c ================
        for (int idx = tid; idx < 2048; idx += THREADS) {
            const int pix = idx * 2;
            const int r = pix >> 6, c = pix & 63;
            const float x0 = pb[pix * 3 + ch],     y0 = gb[pix * 3 + ch];
            const float x1 = pb[pix * 3 + 3 + ch], y1 = gb[pix * 3 + 3 + ch];
            const float u0 = x0 + y0, v0 = x0 - y0;
            const float u1 = x1 + y1, v1 = x1 - y1;
            sts32(AB + swz(r,       c * 2), pk_bf(u1, u0));
            sts32(AB + swz(64 + r,  c * 2), pk_bf(v1, v0));
            sts32(AB + swz(128 + r, c * 2), pk_bf(u1 * u1, u0 * u0));
            sts32(AB + swz(192 + r, c * 2), pk_bf(v1 * v1, v0 * v0));
        }
        __syncthreads();

        // ================= GEMM1 (horizontal), m-half at a time ===========
        // band: n-tile j range per k-tile kt; j=7 (n 56..63, all-zero W) pruned
        {
            #pragma unroll
            for (int mi = 0; mi < 2; ++mi) {
                const int m0 = warp * 32 + mi * 16;
                float acc[7][4] = {};
                #pragma unroll
                for (int kt = 0; kt < 4; ++kt) {
                    const int JST[4] = {0, 0, 2, 4};
                    const int JCN[4] = {2, 4, 4, 3};
                    uint32_t af[4];
                    {
                        const int row  = m0 + (lane & 15);
                        const int colb = kt * 32 + (lane >> 4) * 16;
                        ldm_x4(af, AB + swz(row, colb));
                    }
                    uint32_t bh[4][2], bl[4][2];
                    #pragma unroll
                    for (int jj = 0; jj < 4; ++jj) {
                        if (jj < JCN[kt]) {
                            const int nrow = 8 * (JST[kt] + jj) + (lane & 7);
                            const int colb = kt * 32 + ((lane >> 3) & 1) * 16;
                            ldm_x2(bh[jj], WB  + swz(nrow, colb));
                            ldm_x2(bl[jj], WLB + swz(nrow, colb));
                        }
                    }
                    #pragma unroll
                    for (int jj = 0; jj < 4; ++jj) {
                        if (jj < JCN[kt]) {
                            const int j = JST[kt] + jj;
                            mma16816(acc[j], af, bh[jj]);
                            mma16816(acc[j], af, bl[jj]);
                        }
                    }
                }
                // store C1 rows (warp-private; cols 0..55, rest masked later)
                const int r0 = m0 + g;
                #pragma unroll
                for (int j = 0; j < 7; ++j) {
                    const int colb = j * 16 + tig * 4;
                    sts32(AB + swz(r0,     colb), pk_bf(acc[j][1], acc[j][0]));
                    sts32(AB + swz(r0 + 8, colb), pk_bf(acc[j][3], acc[j][2]));
                }
            }
        }
        __syncthreads();

        // ================= GEMM2 (vertical) + epilogue ====================
        {
            const int mh = warp & 1;     // rows 32*mh..
            const int nq = warp >> 1;    // cols 16*nq..

            // W fragments, hoisted: combos (mi, t) -> kt = 2*mh+mi+t
            uint32_t wh[4][4], wl[4][4];
            #pragma unroll
            for (int mi = 0; mi < 2; ++mi) {
                const int mt = 2 * mh + mi;
                #pragma unroll
                for (int t = 0; t < 2; ++t) {
                    const int kt = mt + t;
                    if (kt < 4) {
                        const int row  = mt * 16 + (lane & 15);
                        const int colb = kt * 32 + (lane >> 4) * 16;
                        ldm_x4(wh[2 * mi + t], WB  + swz(row, colb));
                        ldm_x4(wl[2 * mi + t], WLB + swz(row, colb));
                    }
                }
            }

            #pragma unroll
            for (int nn = 0; nn < 2; ++nn) {
                float acc[4][2][4] = {};
                #pragma unroll
                for (int krel = 0; krel < 3; ++krel) {
                    const int kt = 2 * mh + krel;
                    if (kt < 4) {
                        uint32_t bf[4][2];
                        #pragma unroll
                        for (int s = 0; s < 4; ++s) {
                            const int srow = s * 64 + kt * 16 + (lane & 15);
                            const int colb = (2 * nq + nn) * 16;
                            ldm_x2t(bf[s], AB + swz(srow, colb));
                        }
                        #pragma unroll
                        for (int s = 0; s < 4; ++s) {
                            if (krel <= 1) {     // mi=0 frag index = krel
                                mma16816(acc[s][0], wh[krel], bf[s]);
                                mma16816(acc[s][0], wl[krel], bf[s]);
                            }
                            if (krel >= 1) {     // mi=1 frag index = krel+1
                                mma16816(acc[s][1], wh[krel + 1], bf[s]);
                                mma16816(acc[s][1], wl[krel + 1], bf[s]);
                            }
                        }
                    }
                }
                // epilogue for this n-half
                #pragma unroll
                for (int mi = 0; mi < 2; ++mi) {
                    const int m0e = 32 * mh + 16 * mi;
                    const int n0e = (2 * nq + nn) * 8;
                    #pragma unroll
                    for (int e = 0; e < 4; ++e) {
                        const int r = m0e + g + ((e >= 2) ? 8 : 0);
                        const int c = n0e + 2 * tig + (e & 1);
                        if (r < 54 && c < 54) {
                            const float p  = acc[0][mi][e];
                            const float q  = acc[1][mi][e];
                            const float su = acc[2][mi][e];
                            const float sv = acc[3][mi][e];
                            const float P = p * p, Q = q * q;
                            const float A = 0.5f * (P - Q);
                            const float B = 0.5f * (P + Q);
                            const float num = (A + C1c) * (fmaf(0.5f, su - sv, C2c) - A);
                            const float den = (B + C1c) * (fmaf(0.5f, su + sv, C2c) - B);
                            local += __fdividef(num, den);
                        }
                    }
                }
            }
        }
    }

    // ================= deterministic reduction ============================
    __syncthreads();
    #pragma unroll
    for (int off = 16; off > 0; off >>= 1)
        local += __shfl_down_sync(0xffffffffu, local, off);
    if (lane == 0) red[warp] = local;
    __syncthreads();
    if (tid == 0) {
        float sum = 0.0f;
        #pragma unroll
        for (int w = 0; w < THREADS / 32; ++w) sum += red[w];
        g_part[blockIdx.x] = sum;
        __threadfence();
        ticket = atomicAdd(&g_count, 1u);
    }
    __syncthreads();

    if (ticket == NBLK - 1) {
        float sum = 0.0f;
        for (int i = tid; i < NBLK; i += THREADS) sum += g_part[i];
        #pragma unroll
        for (int off = 16; off > 0; off >>= 1)
            sum += __shfl_down_sync(0xffffffffu, sum, off);
        if (lane == 0) red[warp] = sum;
        __syncthreads();
        if (tid == 0) {
            float t = 0.0f;
            #pragma unroll
            for (int w = 0; w < THREADS / 32; ++w) t += red[w];
            out[0] = 1.0f - t * (1.0f / 17915904.0f);   // 2048*3*54*54
            g_count = 0;                                 // reset for replay
        }
    }
}

extern "C" void kernel_launch(void* const* d_in, const int* in_sizes, int n_in,
                              void* d_out, int out_size)
{
    const float* pred = (const float*)d_in[0];
    const float* gt   = (const float*)d_in[1];
    float* out        = (float*)d_out;

    cudaFuncSetAttribute(ssim_main, cudaFuncAttributeMaxDynamicSharedMemorySize,
                         SMEM_BYTES);
    ssim_main<<<NBLK, THREADS, SMEM_BYTES>>>(pred, gt, out);
}